// round 2
// baseline (speedup 1.0000x reference)
#include <cuda_runtime.h>
#include <math.h>

#define H      2048
#define E      8
#define HV     (H / 4)         // 512 x 16B vectors per row
#define TPW    4               // tokens per warp
#define NWARPS 8
#define TPB    (TPW * NWARPS)  // 32 tokens per block
#define NTHR   256
#define ALPHA  0.01f

// global accumulators: [0..7] = expert counts, [8..15] = sum of softmax probs
__device__ float        g_acc[2 * E];
__device__ unsigned int g_done = 0;

// packed 2xf32 FMA (Blackwell): d = a*b + d, elementwise on the two lanes
__device__ __forceinline__ void ffma2(unsigned long long& d,
                                      unsigned long long a,
                                      unsigned long long b)
{
    asm("fma.rn.f32x2 %0, %1, %2, %0;" : "+l"(d) : "l"(a), "l"(b));
}

__device__ __forceinline__ float pair_sum(unsigned long long p)
{
    float lo, hi;
    asm("mov.b64 {%0, %1}, %2;" : "=f"(lo), "=f"(hi) : "l"(p));
    return lo + hi;
}

__global__ __launch_bounds__(NTHR)
void moe_gate_kernel(const float* __restrict__ x,
                     const float* __restrict__ w,
                     float* __restrict__ out_idx,   // T*2 floats
                     float* __restrict__ out_wgt,   // T*2 floats
                     float* __restrict__ out_aux,   // 1 float
                     int T)
{
    extern __shared__ float smem[];                // E*H floats = 64KB
    const ulonglong2* w8s = reinterpret_cast<const ulonglong2*>(smem);
    __shared__ float s_cnt[E];
    __shared__ float s_psum[E];
    __shared__ unsigned int s_last;

    const int tid  = threadIdx.x;
    const int warp = tid >> 5;
    const int lane = tid & 31;

    if (tid < E)            s_cnt[tid] = 0.0f;
    else if (tid < 2 * E)   s_psum[tid - E] = 0.0f;

    // stage weight [E,H] into smem (16B vectors)
    {
        float4*       ws = reinterpret_cast<float4*>(smem);
        const float4* wg = reinterpret_cast<const float4*>(w);
        #pragma unroll
        for (int i = 0; i < (E * HV) / NTHR; i++)
            ws[tid + i * NTHR] = wg[tid + i * NTHR];
    }
    __syncthreads();

    const int tok0 = blockIdx.x * TPB + warp * TPW;
    const ulonglong2* x8 = reinterpret_cast<const ulonglong2*>(x);

    unsigned long long acc2[TPW][E];    // each holds 2 packed partial sums
    #pragma unroll
    for (int t = 0; t < TPW; t++)
        #pragma unroll
        for (int e = 0; e < E; e++)
            acc2[t][e] = 0ull;

    #pragma unroll 2
    for (int it = 0; it < HV / 32; it++) {
        const int idx = it * 32 + lane;
        ulonglong2 xv[TPW];
        #pragma unroll
        for (int t = 0; t < TPW; t++)
            xv[t] = x8[(size_t)(tok0 + t) * HV + idx];
        #pragma unroll
        for (int e = 0; e < E; e++) {
            const ulonglong2 wv = w8s[e * HV + idx];
            #pragma unroll
            for (int t = 0; t < TPW; t++) {
                ffma2(acc2[t][e], xv[t].x, wv.x);
                ffma2(acc2[t][e], xv[t].y, wv.y);
            }
        }
    }

    // unpack + warp tree-reduce (all lanes end with full sums)
    float accf[TPW][E];
    #pragma unroll
    for (int t = 0; t < TPW; t++)
        #pragma unroll
        for (int e = 0; e < E; e++) {
            float v = pair_sum(acc2[t][e]);
            v += __shfl_xor_sync(0xffffffffu, v, 16);
            v += __shfl_xor_sync(0xffffffffu, v, 8);
            v += __shfl_xor_sync(0xffffffffu, v, 4);
            v += __shfl_xor_sync(0xffffffffu, v, 2);
            v += __shfl_xor_sync(0xffffffffu, v, 1);
            accf[t][e] = v;
        }

    if (lane < TPW) {
        const int tok = tok0 + lane;
        float lg[E];
        #pragma unroll
        for (int e = 0; e < E; e++) lg[e] = accf[lane][e];

        // softmax
        float m = lg[0];
        #pragma unroll
        for (int e = 1; e < E; e++) m = fmaxf(m, lg[e]);
        float p[E];
        float s = 0.0f;
        #pragma unroll
        for (int e = 0; e < E; e++) { p[e] = __expf(lg[e] - m); s += p[e]; }
        const float inv = 1.0f / s;

        // top-2 on logits; ties -> lowest index first
        int i1 = 0; float b1 = lg[0];
        #pragma unroll
        for (int e = 1; e < E; e++)
            if (lg[e] > b1) { b1 = lg[e]; i1 = e; }
        int i2 = -1; float b2 = -INFINITY;
        #pragma unroll
        for (int e = 0; e < E; e++)
            if (e != i1 && lg[e] > b2) { b2 = lg[e]; i2 = e; }

        out_idx[2 * tok]     = (float)i1;
        out_idx[2 * tok + 1] = (float)i2;
        out_wgt[2 * tok]     = p[i1] * inv;
        out_wgt[2 * tok + 1] = p[i2] * inv;

        atomicAdd(&s_cnt[i1], 1.0f);
        atomicAdd(&s_cnt[i2], 1.0f);
        #pragma unroll
        for (int e = 0; e < E; e++)
            atomicAdd(&s_psum[e], p[e] * inv);
    }

    __syncthreads();
    if (tid < E) {
        atomicAdd(&g_acc[tid], s_cnt[tid]);
        __threadfence();
    } else if (tid < 2 * E) {
        atomicAdd(&g_acc[tid], s_psum[tid - E]);
        __threadfence();
    }
    __syncthreads();

    // fused finalize: last block computes aux_loss and resets accumulators
    if (tid == 0)
        s_last = (atomicAdd(&g_done, 1u) == gridDim.x - 1) ? 1u : 0u;
    __syncthreads();

    if (s_last && tid == 0) {
        float aux = 0.0f;
        const float invT  = 1.0f / (float)T;
        const float invTK = 1.0f / ((float)T * 2.0f);
        #pragma unroll
        for (int e = 0; e < E; e++) {
            const float cnt  = atomicAdd(&g_acc[e], 0.0f);       // coherent read
            const float psum = atomicAdd(&g_acc[E + e], 0.0f);
            const float Pi = psum * invT;
            const float fi = cnt * invTK * (float)E;
            aux += Pi * fi;
        }
        out_aux[0] = aux * ALPHA;
        // reset for the next (graph-replayed) run
        #pragma unroll
        for (int i = 0; i < 2 * E; i++) {
            float old = atomicAdd(&g_acc[i], 0.0f);
            atomicAdd(&g_acc[i], -old);
        }
        atomicExch(&g_done, 0u);
    }
}

extern "C" void kernel_launch(void* const* d_in, const int* in_sizes, int n_in,
                              void* d_out, int out_size)
{
    const float* x = (const float*)d_in[0];   // [T, H] flattened
    const float* w = (const float*)d_in[1];   // [E, H]
    const int T = in_sizes[0] / H;            // 16384

    float* out = (float*)d_out;
    float* out_idx = out;                     // [T,2]
    float* out_wgt = out + (size_t)T * 2;     // [T,2]
    float* out_aux = out + (size_t)T * 4;     // [1]

    const int smem_bytes = E * H * (int)sizeof(float);   // 64KB
    cudaFuncSetAttribute(moe_gate_kernel,
                         cudaFuncAttributeMaxDynamicSharedMemorySize, smem_bytes);

    moe_gate_kernel<<<T / TPB, NTHR, smem_bytes>>>(x, w, out_idx, out_wgt, out_aux, T);
}

// round 3
// speedup vs baseline: 1.2870x; 1.2870x over previous
#include <cuda_runtime.h>
#include <math.h>

#define H      2048
#define E      8
#define HV     (H / 4)         // 512 x 16B vectors per row
#define TPW    2               // tokens per warp (keeps regs ~60)
#define NWARPS 16
#define TPB    (TPW * NWARPS)  // 32 tokens per block
#define NTHR   512
#define ALPHA  0.01f

// global accumulators: [0..7] = expert counts, [8..15] = sum of softmax probs
__device__ float        g_acc[2 * E];
__device__ unsigned int g_done = 0;

// packed 2xf32 FMA (Blackwell): d = a*b + d elementwise on both 32-bit lanes
__device__ __forceinline__ void ffma2(unsigned long long& d,
                                      unsigned long long a,
                                      unsigned long long b)
{
    asm("fma.rn.f32x2 %0, %1, %2, %0;" : "+l"(d) : "l"(a), "l"(b));
}

__device__ __forceinline__ float pair_sum(unsigned long long p)
{
    float lo, hi;
    asm("mov.b64 {%0, %1}, %2;" : "=f"(lo), "=f"(hi) : "l"(p));
    return lo + hi;
}

__global__ __launch_bounds__(NTHR, 2)
void moe_gate_kernel(const float* __restrict__ x,
                     const float* __restrict__ w,
                     float* __restrict__ out_idx,   // T*2 floats
                     float* __restrict__ out_wgt,   // T*2 floats
                     float* __restrict__ out_aux,   // 1 float
                     int T)
{
    extern __shared__ float smem[];                // E*H floats = 64KB
    const ulonglong2* w8s = reinterpret_cast<const ulonglong2*>(smem);
    __shared__ float s_cnt[E];
    __shared__ float s_psum[E];
    __shared__ unsigned int s_last;

    const int tid  = threadIdx.x;
    const int warp = tid >> 5;
    const int lane = tid & 31;

    if (tid < E)            s_cnt[tid] = 0.0f;
    else if (tid < 2 * E)   s_psum[tid - E] = 0.0f;

    // stage weight [E,H] into smem (16B vectors): 4096 vectors / 512 thr = 8 rounds
    {
        float4*       ws = reinterpret_cast<float4*>(smem);
        const float4* wg = reinterpret_cast<const float4*>(w);
        #pragma unroll
        for (int i = 0; i < (E * HV) / NTHR; i++)
            ws[tid + i * NTHR] = wg[tid + i * NTHR];
    }
    __syncthreads();

    const int tok0 = blockIdx.x * TPB + warp * TPW;
    const ulonglong2* x8a = reinterpret_cast<const ulonglong2*>(x) + (size_t)tok0 * HV + lane;
    const ulonglong2* x8b = x8a + HV;

    unsigned long long acc2[TPW][E];    // each holds 2 packed partial sums
    #pragma unroll
    for (int t = 0; t < TPW; t++)
        #pragma unroll
        for (int e = 0; e < E; e++)
            acc2[t][e] = 0ull;

    #pragma unroll 4
    for (int it = 0; it < HV / 32; it++) {
        const ulonglong2 xv0 = x8a[it * 32];
        const ulonglong2 xv1 = x8b[it * 32];
        const int idx = it * 32 + lane;
        #pragma unroll
        for (int e = 0; e < E; e++) {
            const ulonglong2 wv = w8s[e * HV + idx];
            ffma2(acc2[0][e], xv0.x, wv.x);
            ffma2(acc2[0][e], xv0.y, wv.y);
            ffma2(acc2[1][e], xv1.x, wv.x);
            ffma2(acc2[1][e], xv1.y, wv.y);
        }
    }

    // unpack + warp tree-reduce (all lanes end with full sums)
    float accf[TPW][E];
    #pragma unroll
    for (int t = 0; t < TPW; t++)
        #pragma unroll
        for (int e = 0; e < E; e++) {
            float v = pair_sum(acc2[t][e]);
            v += __shfl_xor_sync(0xffffffffu, v, 16);
            v += __shfl_xor_sync(0xffffffffu, v, 8);
            v += __shfl_xor_sync(0xffffffffu, v, 4);
            v += __shfl_xor_sync(0xffffffffu, v, 2);
            v += __shfl_xor_sync(0xffffffffu, v, 1);
            accf[t][e] = v;
        }

    if (lane < TPW) {
        const int tok = tok0 + lane;
        float lg[E];
        #pragma unroll
        for (int e = 0; e < E; e++) lg[e] = accf[lane][e];

        // softmax
        float m = lg[0];
        #pragma unroll
        for (int e = 1; e < E; e++) m = fmaxf(m, lg[e]);
        float p[E];
        float s = 0.0f;
        #pragma unroll
        for (int e = 0; e < E; e++) { p[e] = __expf(lg[e] - m); s += p[e]; }
        const float inv = 1.0f / s;

        // top-2 on logits; ties -> lowest index first
        int i1 = 0; float b1 = lg[0];
        #pragma unroll
        for (int e = 1; e < E; e++)
            if (lg[e] > b1) { b1 = lg[e]; i1 = e; }
        int i2 = -1; float b2 = -INFINITY;
        #pragma unroll
        for (int e = 0; e < E; e++)
            if (e != i1 && lg[e] > b2) { b2 = lg[e]; i2 = e; }

        out_idx[2 * tok]     = (float)i1;
        out_idx[2 * tok + 1] = (float)i2;
        out_wgt[2 * tok]     = p[i1] * inv;
        out_wgt[2 * tok + 1] = p[i2] * inv;

        atomicAdd(&s_cnt[i1], 1.0f);
        atomicAdd(&s_cnt[i2], 1.0f);
        #pragma unroll
        for (int e = 0; e < E; e++)
            atomicAdd(&s_psum[e], p[e] * inv);
    }

    __syncthreads();
    if (tid < E)           atomicAdd(&g_acc[tid], s_cnt[tid]);
    else if (tid < 2 * E)  atomicAdd(&g_acc[tid], s_psum[tid - E]);
    __threadfence();
    __syncthreads();

    // fused finalize: last block computes aux_loss and resets accumulators
    if (tid == 0)
        s_last = (atomicAdd(&g_done, 1u) == gridDim.x - 1) ? 1u : 0u;
    __syncthreads();

    if (s_last && tid == 0) {
        float aux = 0.0f;
        const float invT  = 1.0f / (float)T;
        const float invTK = 1.0f / ((float)T * 2.0f);
        #pragma unroll
        for (int e = 0; e < E; e++) {
            const float cnt  = atomicAdd(&g_acc[e], 0.0f);       // coherent read
            const float psum = atomicAdd(&g_acc[E + e], 0.0f);
            const float Pi = psum * invT;
            const float fi = cnt * invTK * (float)E;
            aux += Pi * fi;
        }
        out_aux[0] = aux * ALPHA;
        // reset for the next (graph-replayed) run
        #pragma unroll
        for (int i = 0; i < 2 * E; i++) {
            float old = atomicAdd(&g_acc[i], 0.0f);
            atomicAdd(&g_acc[i], -old);
        }
        atomicExch(&g_done, 0u);
    }
}

extern "C" void kernel_launch(void* const* d_in, const int* in_sizes, int n_in,
                              void* d_out, int out_size)
{
    const float* x = (const float*)d_in[0];   // [T, H] flattened
    const float* w = (const float*)d_in[1];   // [E, H]
    const int T = in_sizes[0] / H;            // 16384

    float* out = (float*)d_out;
    float* out_idx = out;                     // [T,2]
    float* out_wgt = out + (size_t)T * 2;     // [T,2]
    float* out_aux = out + (size_t)T * 4;     // [1]

    const int smem_bytes = E * H * (int)sizeof(float);   // 64KB
    cudaFuncSetAttribute(moe_gate_kernel,
                         cudaFuncAttributeMaxDynamicSharedMemorySize, smem_bytes);

    moe_gate_kernel<<<T / TPB, NTHR, smem_bytes>>>(x, w, out_idx, out_wgt, out_aux, T);
}